// round 1
// baseline (speedup 1.0000x reference)
#include <cuda_runtime.h>

// Problem: x [2048, 17, 64, 32] fp32.
// 1) antialiased linear resize (jax.image.resize 'linear', factor 1/4 both dims)
//    == separable 8-tap triangle filter, interior weights {1,3,5,7,7,5,3,1}/32,
//    border outputs renormalized by /28 instead of /32.
// 2) per (n,c): max + argmax over 16*8=128 spatial; max_index = (idx%8, idx/8) as float
// 3) groups [0..4],[5..10],[11..16]: heatmap = sum over group channels,
//    max_response_2 = mean of per-channel maxes
// 4) softmax over the 128 spatial positions per (n, group)
// Outputs concatenated fp32: heatmap [2048,3,16,8] (786432), max_response_2 [2048,3]
// (6144), max_index [2048,17,2] (69632). Total 862208.

#define TILE_STRIDE 37   // 32 data cols + 2 zero pad each side (36) + 1 anti-conflict
#define HBUF_STRIDE 9    // 8 cols + 1 pad
#define W32(k) (k)        // helper

__global__ __launch_bounds__(256, 8)
void heatmap_kernel(const float* __restrict__ x, float* __restrict__ out)
{
    __shared__ float tile[64 * TILE_STRIDE];   // padded rows: col c at (c+2)
    __shared__ float hbuf[68 * HBUF_STRIDE];   // padded rows: row r at (r+2)
    __shared__ float red[8];
    __shared__ int   redi[4];
    __shared__ float chmax[17];
    __shared__ int   chidx[17];

    const int tid = threadIdx.x;
    const int n   = blockIdx.x;

    // ---- zero the padded borders once (they are never overwritten) ----
    // tile: cols 0,1 and 34,35 of all 64 rows  (256 entries)
    {
        int r = tid >> 2;
        int c = tid & 3;
        int col = (c < 2) ? c : (32 + c);      // 0,1,34,35
        tile[r * TILE_STRIDE + col] = 0.f;
    }
    // hbuf: padded rows 0,1 and 66,67 (cols 0..7)
    if (tid < 32) {
        int r  = tid >> 3;                      // 0..3
        int rr = (r < 2) ? r : (64 + r);        // 0,1,66,67
        hbuf[rr * HBUF_STRIDE + (tid & 7)] = 0.f;
    }

    const int oh = tid >> 3;   // 0..15 (valid for tid<128)
    const int ow = tid & 7;    // 0..7
    // combined edge-renormalization scale (32/28 per edge dimension)
    const float sc = (((oh == 0) | (oh == 15)) ? (32.f / 28.f) : 1.f)
                   * (((ow == 0) | (ow == 7))  ? (32.f / 28.f) : 1.f);

    float gs0 = 0.f, gs1 = 0.f, gs2 = 0.f;

    const float4* __restrict__ src =
        (const float4*)(x + (size_t)n * 17 * 2048);

    for (int ch = 0; ch < 17; ++ch) {
        // ---- load 64x32 tile (512 float4, 2 per thread), scatter into padded smem
        #pragma unroll
        for (int q = tid; q < 512; q += 256) {
            float4 v = src[ch * 512 + q];
            int r  = q >> 3;
            int c4 = (q & 7) << 2;
            float* t = &tile[r * TILE_STRIDE + 2 + c4];
            t[0] = v.x; t[1] = v.y; t[2] = v.z; t[3] = v.w;
        }
        __syncthreads();

        // ---- horizontal 8-tap: 64 rows x 8 out-cols = 512 outputs, 2 per thread
        #pragma unroll
        for (int q = tid; q < 512; q += 256) {
            int r = q >> 3;
            int w = q & 7;
            const float* t = &tile[r * TILE_STRIDE + 4 * w];  // cols (4w-2..4w+5)+2pad
            float acc = t[0] * (1.f / 32.f) + t[1] * (3.f / 32.f)
                      + t[2] * (5.f / 32.f) + t[3] * (7.f / 32.f)
                      + t[4] * (7.f / 32.f) + t[5] * (5.f / 32.f)
                      + t[6] * (3.f / 32.f) + t[7] * (1.f / 32.f);
            hbuf[(r + 2) * HBUF_STRIDE + w] = acc;
        }
        __syncthreads();

        // ---- vertical 8-tap + per-channel max/argmax (threads 0..127)
        if (tid < 128) {
            const float* h = &hbuf[(4 * oh) * HBUF_STRIDE + ow]; // rows (4oh-2..)+2pad
            float acc = h[0 * HBUF_STRIDE] * (1.f / 32.f)
                      + h[1 * HBUF_STRIDE] * (3.f / 32.f)
                      + h[2 * HBUF_STRIDE] * (5.f / 32.f)
                      + h[3 * HBUF_STRIDE] * (7.f / 32.f)
                      + h[4 * HBUF_STRIDE] * (7.f / 32.f)
                      + h[5 * HBUF_STRIDE] * (5.f / 32.f)
                      + h[6 * HBUF_STRIDE] * (3.f / 32.f)
                      + h[7 * HBUF_STRIDE] * (1.f / 32.f);
            float val = acc * sc;

            if (ch < 5)       gs0 += val;
            else if (ch < 11) gs1 += val;
            else              gs2 += val;

            // warp argmax (first-occurrence tie-break: lower index wins on equal)
            float m  = val;
            int   mi = tid;
            #pragma unroll
            for (int off = 16; off; off >>= 1) {
                float om = __shfl_down_sync(0xffffffffu, m,  off);
                int   oi = __shfl_down_sync(0xffffffffu, mi, off);
                if (om > m || (om == m && oi < mi)) { m = om; mi = oi; }
            }
            if ((tid & 31) == 0) { red[tid >> 5] = m; redi[tid >> 5] = mi; }
        }
        __syncthreads();
        if (tid == 0) {
            float m = red[0]; int mi = redi[0];
            #pragma unroll
            for (int wv = 1; wv < 4; ++wv)
                if (red[wv] > m || (red[wv] == m && redi[wv] < mi)) {
                    m = red[wv]; mi = redi[wv];
                }
            chmax[ch] = m; chidx[ch] = mi;
        }
        __syncthreads();
    }

    // ---- softmax per group over 128 spatial positions ----
    float g[3] = { gs0, gs1, gs2 };
    const size_t base_h = (size_t)n * 3 * 128;

    #pragma unroll
    for (int gi = 0; gi < 3; ++gi) {
        float v = (tid < 128) ? g[gi] : -1e30f;
        float m = v;
        #pragma unroll
        for (int off = 16; off; off >>= 1)
            m = fmaxf(m, __shfl_down_sync(0xffffffffu, m, off));
        if (tid < 128 && (tid & 31) == 0) red[tid >> 5] = m;
        __syncthreads();
        float bm = fmaxf(fmaxf(red[0], red[1]), fmaxf(red[2], red[3]));
        float e = (tid < 128) ? __expf(v - bm) : 0.f;
        float s = e;
        #pragma unroll
        for (int off = 16; off; off >>= 1)
            s += __shfl_down_sync(0xffffffffu, s, off);
        if (tid < 128 && (tid & 31) == 0) red[4 + (tid >> 5)] = s;
        __syncthreads();
        if (tid < 128) {
            float tot = red[4] + red[5] + red[6] + red[7];
            out[base_h + (size_t)gi * 128 + tid] = e / tot;
        }
        __syncthreads();
    }

    // ---- max_response_2: group means of per-channel maxes ----
    if (tid < 3) {
        float s = 0.f;
        if (tid == 0) {
            #pragma unroll
            for (int c2 = 0; c2 < 5; ++c2) s += chmax[c2];
            s *= (1.f / 5.f);
        } else if (tid == 1) {
            #pragma unroll
            for (int c2 = 5; c2 < 11; ++c2) s += chmax[c2];
            s *= (1.f / 6.f);
        } else {
            #pragma unroll
            for (int c2 = 11; c2 < 17; ++c2) s += chmax[c2];
            s *= (1.f / 6.f);
        }
        out[786432 + (size_t)n * 3 + tid] = s;
    }

    // ---- max_index: (idx % 8, idx / 8) as floats ----
    if (tid < 17) {
        int mi = chidx[tid];
        size_t o = 792576 + ((size_t)n * 17 + tid) * 2;
        out[o + 0] = (float)(mi & 7);
        out[o + 1] = (float)(mi >> 3);
    }
}

extern "C" void kernel_launch(void* const* d_in, const int* in_sizes, int n_in,
                              void* d_out, int out_size)
{
    const float* x = (const float*)d_in[0];
    float* out = (float*)d_out;
    (void)in_sizes; (void)n_in; (void)out_size;
    heatmap_kernel<<<2048, 256>>>(x, out);
}

// round 2
// speedup vs baseline: 1.2334x; 1.2334x over previous
#include <cuda_runtime.h>

// x [2048, 17, 64, 32] fp32 ->
//  heatmap      [2048,3,16,8]  (softmax over 128 of group-summed resized maps)
//  max_response [2048,3]       (group mean of per-channel maxes of resized maps)
//  max_index    [2048,17,2]    ((idx%8, idx/8) of per-channel argmax)
// resize = jax.image.resize 'linear' (antialias) 1/4 both dims:
//  separable 8-tap triangle {1,3,5,7,7,5,3,1}/32, border outputs renorm x(32/28).
//
// Layout: 1 CTA per n, 17 warps (one per channel). Each lane = one column.
// Vertical 8-tap streamed from global in registers (16 accumulators),
// horizontal 8-tap via a tiny per-warp smem transpose. Group sums via smem
// atomicAdd. Only 3 block-wide barriers per CTA.

#define VB_STRIDE 37   // 32 cols + 2 zero pad each side + 1 anti-conflict

__global__ __launch_bounds__(544, 2)
void heatmap_kernel(const float* __restrict__ x, float* __restrict__ out)
{
    __shared__ float vbuf[17 * 16 * VB_STRIDE];  // per-warp 16 x 37 padded
    __shared__ float gsum[3 * 128];
    __shared__ float chmax[17];
    __shared__ int   chidx[17];
    __shared__ float red[8];

    const int tid  = threadIdx.x;
    const int ch   = tid >> 5;      // warp id == channel (0..16)
    const int lane = tid & 31;      // column
    const int n    = blockIdx.x;

    const float W0 = 1.f / 32.f, W1 = 3.f / 32.f, W2 = 5.f / 32.f, W3 = 7.f / 32.f;
    const float Wt[8] = { W0, W1, W2, W3, W3, W2, W1, W0 };

    // zero gsum (shared across warps) and per-warp pad columns
    if (tid < 384) gsum[tid] = 0.f;
    float* wb = &vbuf[ch * 16 * VB_STRIDE];
    {
        int vr = lane >> 1;
        int o  = (lane & 1) ? 34 : 0;          // pad idx pairs {0,1} and {34,35}
        wb[vr * VB_STRIDE + o]     = 0.f;
        wb[vr * VB_STRIDE + o + 1] = 0.f;
    }
    __syncthreads();   // barrier #1: gsum zeroed before any atomicAdd

    // ---- vertical 8-tap, streamed: 64 coalesced row loads, 16 reg accumulators
    const float* __restrict__ g = x + ((size_t)n * 17 + ch) * 2048 + lane;

    float vacc[16];
    #pragma unroll
    for (int i = 0; i < 16; ++i) vacc[i] = 0.f;

    #pragma unroll
    for (int r = 0; r < 64; ++r) {
        float v = __ldg(g + r * 32);
        const int vr_a = (r + 2) >> 2;         // compile-time after unroll
        const int k_a  = r - 4 * vr_a + 2;     // 0..3
        if (vr_a < 16) vacc[vr_a]     += Wt[k_a]     * v;
        if (vr_a >= 1) vacc[vr_a - 1] += Wt[k_a + 4] * v;
    }

    #pragma unroll
    for (int vr = 0; vr < 16; ++vr)
        wb[vr * VB_STRIDE + 2 + lane] = vacc[vr];
    __syncwarp();

    // ---- horizontal 8-tap: lane owns spatial outputs s = 4*lane + j (j=0..3)
    const int vr  = lane >> 1;
    const int grp = (ch < 5) ? 0 : (ch < 11 ? 1 : 2);
    const float sc_v = ((vr == 0) | (vr == 15)) ? (32.f / 28.f) : 1.f;

    float mval = -1e30f;
    int   midx = 0;
    #pragma unroll
    for (int j = 0; j < 4; ++j) {
        const int ow = 4 * (lane & 1) + j;
        const float* h = &wb[vr * VB_STRIDE + 4 * ow];  // cols (4ow-2..4ow+5)+2pad
        float acc = h[0] * W0 + h[1] * W1 + h[2] * W2 + h[3] * W3
                  + h[4] * W3 + h[5] * W2 + h[6] * W1 + h[7] * W0;
        const float sc = sc_v * (((ow == 0) | (ow == 7)) ? (32.f / 28.f) : 1.f);
        const float val = acc * sc;
        const int s = vr * 8 + ow;             // == 4*lane + j, ascending in j
        atomicAdd(&gsum[grp * 128 + s], val);
        if (val > mval) { mval = val; midx = s; }
    }

    // warp argmax (first-occurrence tie-break)
    #pragma unroll
    for (int off = 16; off; off >>= 1) {
        float om = __shfl_down_sync(0xffffffffu, mval, off);
        int   oi = __shfl_down_sync(0xffffffffu, midx, off);
        if (om > mval || (om == mval && oi < midx)) { mval = om; midx = oi; }
    }
    if (lane == 0) { chmax[ch] = mval; chidx[ch] = midx; }

    __syncthreads();   // barrier #2: gsum + chmax/chidx complete

    // ---- softmax per group over 128 spatial positions (threads 0..127 active)
    const size_t base_h = (size_t)n * 384;
    #pragma unroll
    for (int gi = 0; gi < 3; ++gi) {
        float v = (tid < 128) ? gsum[gi * 128 + tid] : -1e30f;
        float m = v;
        #pragma unroll
        for (int off = 16; off; off >>= 1)
            m = fmaxf(m, __shfl_down_sync(0xffffffffu, m, off));
        if (tid < 128 && lane == 0) red[tid >> 5] = m;
        __syncthreads();
        const float bm = fmaxf(fmaxf(red[0], red[1]), fmaxf(red[2], red[3]));
        const float e = (tid < 128) ? __expf(v - bm) : 0.f;
        float s = e;
        #pragma unroll
        for (int off = 16; off; off >>= 1)
            s += __shfl_down_sync(0xffffffffu, s, off);
        if (tid < 128 && lane == 0) red[4 + (tid >> 5)] = s;
        __syncthreads();
        if (tid < 128) {
            const float tot = red[4] + red[5] + red[6] + red[7];
            out[base_h + (size_t)gi * 128 + tid] = e / tot;
        }
    }

    // ---- max_response_2: group means of per-channel maxes
    if (tid < 3) {
        float s = 0.f;
        if (tid == 0) {
            #pragma unroll
            for (int c = 0; c < 5; ++c) s += chmax[c];
            s *= (1.f / 5.f);
        } else if (tid == 1) {
            #pragma unroll
            for (int c = 5; c < 11; ++c) s += chmax[c];
            s *= (1.f / 6.f);
        } else {
            #pragma unroll
            for (int c = 11; c < 17; ++c) s += chmax[c];
            s *= (1.f / 6.f);
        }
        out[786432 + (size_t)n * 3 + tid] = s;
    }

    // ---- max_index: (idx % 8, idx / 8) as floats
    if (tid < 17) {
        const int mi = chidx[tid];
        const size_t o = 792576 + ((size_t)n * 17 + tid) * 2;
        out[o + 0] = (float)(mi & 7);
        out[o + 1] = (float)(mi >> 3);
    }
}

extern "C" void kernel_launch(void* const* d_in, const int* in_sizes, int n_in,
                              void* d_out, int out_size)
{
    const float* x = (const float*)d_in[0];
    float* out = (float*)d_out;
    (void)in_sizes; (void)n_in; (void)out_size;
    heatmap_kernel<<<2048, 544>>>(x, out);
}

// round 3
// speedup vs baseline: 1.2649x; 1.0255x over previous
#include <cuda_runtime.h>

// x [2048, 17, 64, 32] fp32 ->
//  heatmap      [2048,3,16,8]  softmax over 128 of group-summed resized maps
//  max_response [2048,3]       group mean of per-channel maxes of resized maps
//  max_index    [2048,17,2]    (idx%8, idx/8) of per-channel argmax
// resize = jax.image.resize 'linear' (antialias) 1/4 both dims:
//  separable 8-tap triangle {1,3,5,7,7,5,3,1}/32, border outputs renorm x(32/28).
//
// 1 CTA per n, 17 warps (one per channel), lane = column.
// Vertical 8-tap in registers from 64 coalesced row loads; horizontal 8-tap
// via per-warp smem transpose. Group sums via smem atomicAdd.
// 3 CTAs/SM (launch_bounds caps regs at 40) for phase-staggered DRAM feed.

#define VB_STRIDE 37   // 32 cols + 2 zero pad each side + 1 anti-conflict

__global__ __launch_bounds__(544, 3)
void heatmap_kernel(const float* __restrict__ x, float* __restrict__ out)
{
    __shared__ float vbuf[17 * 16 * VB_STRIDE];  // per-warp 16 x 37 padded
    __shared__ float gsum[3 * 128];
    __shared__ float chmax[17];
    __shared__ int   chidx[17];
    __shared__ float redm[12];
    __shared__ float reds[12];

    const int tid  = threadIdx.x;
    const int ch   = tid >> 5;      // warp id == channel (0..16)
    const int lane = tid & 31;      // column
    const int n    = blockIdx.x;

    const float W0 = 1.f / 32.f, W1 = 3.f / 32.f, W2 = 5.f / 32.f, W3 = 7.f / 32.f;
    const float Wt[8] = { W0, W1, W2, W3, W3, W2, W1, W0 };

    // zero gsum and per-warp pad columns
    if (tid < 384) gsum[tid] = 0.f;
    float* wb = &vbuf[ch * 16 * VB_STRIDE];
    {
        int vr = lane >> 1;
        int o  = (lane & 1) ? 34 : 0;          // pads {0,1} and {34,35}
        wb[vr * VB_STRIDE + o]     = 0.f;
        wb[vr * VB_STRIDE + o + 1] = 0.f;
    }
    __syncthreads();   // barrier #1: gsum zeroed before any atomicAdd

    // ---- vertical 8-tap, streamed: 64 coalesced row loads, 16 reg accumulators
    const float* __restrict__ g = x + ((size_t)n * 17 + ch) * 2048 + lane;

    float vacc[16];
    #pragma unroll
    for (int i = 0; i < 16; ++i) vacc[i] = 0.f;

    #pragma unroll
    for (int r = 0; r < 64; ++r) {
        float v = __ldg(g + r * 32);
        const int vr_a = (r + 2) >> 2;         // compile-time after unroll
        const int k_a  = r - 4 * vr_a + 2;     // 0..3
        if (vr_a < 16) vacc[vr_a]     += Wt[k_a]     * v;
        if (vr_a >= 1) vacc[vr_a - 1] += Wt[k_a + 4] * v;
    }

    #pragma unroll
    for (int vr = 0; vr < 16; ++vr)
        wb[vr * VB_STRIDE + 2 + lane] = vacc[vr];
    __syncwarp();

    // ---- horizontal 8-tap: lane owns spatial outputs s = 4*lane + j
    const int vr  = lane >> 1;
    const int grp = (ch < 5) ? 0 : (ch < 11 ? 1 : 2);
    const float sc_v = ((vr == 0) | (vr == 15)) ? (32.f / 28.f) : 1.f;

    float mval = -1e30f;
    int   midx = 0;
    #pragma unroll
    for (int j = 0; j < 4; ++j) {
        const int ow = 4 * (lane & 1) + j;
        const float* h = &wb[vr * VB_STRIDE + 4 * ow];
        float acc = h[0] * W0 + h[1] * W1 + h[2] * W2 + h[3] * W3
                  + h[4] * W3 + h[5] * W2 + h[6] * W1 + h[7] * W0;
        const float sc = sc_v * (((ow == 0) | (ow == 7)) ? (32.f / 28.f) : 1.f);
        const float val = acc * sc;
        const int s = vr * 8 + ow;
        atomicAdd(&gsum[grp * 128 + s], val);
        if (val > mval) { mval = val; midx = s; }
    }

    // warp argmax (first-occurrence tie-break)
    #pragma unroll
    for (int off = 16; off; off >>= 1) {
        float om = __shfl_down_sync(0xffffffffu, mval, off);
        int   oi = __shfl_down_sync(0xffffffffu, midx, off);
        if (om > mval || (om == mval && oi < midx)) { mval = om; midx = oi; }
    }
    if (lane == 0) { chmax[ch] = mval; chidx[ch] = midx; }

    __syncthreads();   // barrier #2: gsum + chmax/chidx complete

    // ---- epilogue: all 3 group softmaxes in parallel on threads 0..383
    float e = 0.f;
    int gi = tid >> 7;                         // valid for tid<384
    if (tid < 384) {
        float v = gsum[tid];
        float m = v;
        #pragma unroll
        for (int off = 16; off; off >>= 1)
            m = fmaxf(m, __shfl_down_sync(0xffffffffu, m, off));
        if (lane == 0) redm[ch] = m;           // ch == warp id, 0..11 here
        e = v;                                 // stash v in e temporarily
    } else if (tid < 384 + 17) {
        // max_index writes (depend only on chidx, ready at barrier #2)
        const int c = tid - 384;
        const int mi = chidx[c];
        const size_t o = 792576 + ((size_t)n * 17 + c) * 2;
        out[o + 0] = (float)(mi & 7);
        out[o + 1] = (float)(mi >> 3);
    } else if (tid < 384 + 17 + 3) {
        // max_response_2: group means of per-channel maxes
        const int t = tid - (384 + 17);
        float s = 0.f;
        if (t == 0) {
            #pragma unroll
            for (int c = 0; c < 5; ++c) s += chmax[c];
            s *= (1.f / 5.f);
        } else if (t == 1) {
            #pragma unroll
            for (int c = 5; c < 11; ++c) s += chmax[c];
            s *= (1.f / 6.f);
        } else {
            #pragma unroll
            for (int c = 11; c < 17; ++c) s += chmax[c];
            s *= (1.f / 6.f);
        }
        out[786432 + (size_t)n * 3 + t] = s;
    }
    __syncthreads();   // barrier #3: warp maxes in redm

    if (tid < 384) {
        const float bm = fmaxf(fmaxf(redm[4 * gi + 0], redm[4 * gi + 1]),
                               fmaxf(redm[4 * gi + 2], redm[4 * gi + 3]));
        e = __expf(e - bm);
        float s = e;
        #pragma unroll
        for (int off = 16; off; off >>= 1)
            s += __shfl_down_sync(0xffffffffu, s, off);
        if (lane == 0) reds[ch] = s;
    }
    __syncthreads();   // barrier #4: warp sums in reds

    if (tid < 384) {
        const float tot = (reds[4 * gi + 0] + reds[4 * gi + 1])
                        + (reds[4 * gi + 2] + reds[4 * gi + 3]);
        out[(size_t)n * 384 + tid] = e / tot;
    }
}

extern "C" void kernel_launch(void* const* d_in, const int* in_sizes, int n_in,
                              void* d_out, int out_size)
{
    const float* x = (const float*)d_in[0];
    float* out = (float*)d_out;
    (void)in_sizes; (void)n_in; (void)out_size;
    heatmap_kernel<<<2048, 544>>>(x, out);
}

// round 4
// speedup vs baseline: 1.2920x; 1.0214x over previous
#include <cuda_runtime.h>

// x [2048, 17, 64, 32] fp32 ->
//  heatmap      [2048,3,16,8]  softmax over 128 of group-summed resized maps
//  max_response [2048,3]       group mean of per-channel maxes of resized maps
//  max_index    [2048,17,2]    (idx%8, idx/8) of per-channel argmax
// resize = jax.image.resize 'linear' (antialias) 1/4 both dims:
//  separable 8-tap triangle {1,3,5,7,7,5,3,1}/32, border outputs renorm x(32/28).
//
// R4 design: one WARP per (n, group). The warp streams its group's channels
// (5 or 6), does the vertical 8-tap in registers from 64 coalesced row loads,
// horizontal 8-tap via a private 16x37 smem transpose, accumulates the group
// sum in 4 regs/lane, and finishes softmax + all outputs inside the warp.
// ZERO block barriers, zero atomics, warps fully independent.

#define VB_STRIDE 37   // 32 cols + 2 zero pad each side + 1 anti-conflict
#define WARPS_PER_CTA 4

__global__ __launch_bounds__(128, 12)
void heatmap_kernel(const float* __restrict__ x, float* __restrict__ out)
{
    __shared__ float buf[WARPS_PER_CTA][16 * VB_STRIDE];

    const int lane = threadIdx.x & 31;
    const int wrp  = threadIdx.x >> 5;
    const int wid  = blockIdx.x * WARPS_PER_CTA + wrp;   // 0..6143
    const int n    = wid / 3;
    const int g    = wid - 3 * n;                        // group 0..2

    const int ch_beg = (g == 0) ? 0 : (g == 1 ? 5 : 11);
    const int ch_end = (g == 0) ? 5 : (g == 1 ? 11 : 17);

    const float W0 = 1.f / 32.f, W1 = 3.f / 32.f, W2 = 5.f / 32.f, W3 = 7.f / 32.f;
    const float Wt[8] = { W0, W1, W2, W3, W3, W2, W1, W0 };

    float* wb = buf[wrp];

    // zero padded border columns once (cols 0,1 and 34,35 of 16 rows)
    {
        int vr = lane >> 1;
        int o  = (lane & 1) ? 34 : 0;
        wb[vr * VB_STRIDE + o]     = 0.f;
        wb[vr * VB_STRIDE + o + 1] = 0.f;
    }
    __syncwarp();

    const int vr = lane >> 1;
    const float sc_v = ((vr == 0) | (vr == 15)) ? (32.f / 28.f) : 1.f;

    float gacc[4] = { 0.f, 0.f, 0.f, 0.f };   // group sum, outputs s=4*lane+j
    float summax  = 0.f;                       // lane 0: sum of per-channel maxes

    for (int c = ch_beg; c < ch_end; ++c) {
        // ---- vertical 8-tap: 64 coalesced row loads, 16 reg accumulators
        const float* __restrict__ gp = x + ((size_t)n * 17 + c) * 2048 + lane;

        float vacc[16];
        #pragma unroll
        for (int i = 0; i < 16; ++i) vacc[i] = 0.f;

        #pragma unroll
        for (int r = 0; r < 64; ++r) {
            float v = __ldg(gp + r * 32);
            const int vr_a = (r + 2) >> 2;     // compile-time after unroll
            const int k_a  = r - 4 * vr_a + 2; // 0..3
            if (vr_a < 16) vacc[vr_a]     += Wt[k_a]     * v;
            if (vr_a >= 1) vacc[vr_a - 1] += Wt[k_a + 4] * v;
        }

        #pragma unroll
        for (int i = 0; i < 16; ++i)
            wb[i * VB_STRIDE + 2 + lane] = vacc[i];
        __syncwarp();

        // ---- horizontal 8-tap: lane owns spatial outputs s = 4*lane + j
        float mval = -1e30f;
        int   midx = 0;
        #pragma unroll
        for (int j = 0; j < 4; ++j) {
            const int ow = 4 * (lane & 1) + j;
            const float* h = &wb[vr * VB_STRIDE + 4 * ow]; // cols (4ow-2..)+2pad
            float acc = h[0] * W0 + h[1] * W1 + h[2] * W2 + h[3] * W3
                      + h[4] * W3 + h[5] * W2 + h[6] * W1 + h[7] * W0;
            const float sc = sc_v * (((ow == 0) | (ow == 7)) ? (32.f / 28.f) : 1.f);
            const float val = acc * sc;
            gacc[j] += val;
            if (val > mval) { mval = val; midx = 4 * lane + j; }
        }
        __syncwarp();   // protect wb from next channel's STS

        // ---- per-channel warp argmax (first occurrence on ties)
        #pragma unroll
        for (int off = 16; off; off >>= 1) {
            float om = __shfl_down_sync(0xffffffffu, mval, off);
            int   oi = __shfl_down_sync(0xffffffffu, midx, off);
            if (om > mval || (om == mval && oi < midx)) { mval = om; midx = oi; }
        }
        if (lane == 0) {
            summax += mval;
            const size_t o = 792576 + ((size_t)n * 17 + c) * 2;
            out[o + 0] = (float)(midx & 7);
            out[o + 1] = (float)(midx >> 3);
        }
    }

    // ---- warp-local softmax over the 128 group-sum values (4 per lane)
    float m = fmaxf(fmaxf(gacc[0], gacc[1]), fmaxf(gacc[2], gacc[3]));
    #pragma unroll
    for (int off = 16; off; off >>= 1)
        m = fmaxf(m, __shfl_xor_sync(0xffffffffu, m, off));

    float e0 = __expf(gacc[0] - m);
    float e1 = __expf(gacc[1] - m);
    float e2 = __expf(gacc[2] - m);
    float e3 = __expf(gacc[3] - m);
    float s  = (e0 + e1) + (e2 + e3);
    #pragma unroll
    for (int off = 16; off; off >>= 1)
        s += __shfl_xor_sync(0xffffffffu, s, off);

    const float inv = 1.f / s;
    float4 o4;
    o4.x = e0 * inv; o4.y = e1 * inv; o4.z = e2 * inv; o4.w = e3 * inv;
    *(float4*)(out + (size_t)n * 384 + (size_t)g * 128 + 4 * lane) = o4;

    // ---- max_response_2: group mean of per-channel maxes
    if (lane == 0) {
        const float cnt = (g == 0) ? (1.f / 5.f) : (1.f / 6.f);
        out[786432 + (size_t)n * 3 + g] = summax * cnt;
    }
}

extern "C" void kernel_launch(void* const* d_in, const int* in_sizes, int n_in,
                              void* d_out, int out_size)
{
    const float* x = (const float*)d_in[0];
    float* out = (float*)d_out;
    (void)in_sizes; (void)n_in; (void)out_size;
    heatmap_kernel<<<2048 * 3 / WARPS_PER_CTA, 32 * WARPS_PER_CTA>>>(x, out);
}